// round 2
// baseline (speedup 1.0000x reference)
#include <cuda_runtime.h>
#include <cuda_bf16.h>
#include <math.h>

// Problem shape (fixed by the reference)
#define B 32
#define S 4096
#define H 1024
#define CHUNKS 8                       // seq chunks per batch (split-softmax)
#define ROWS_PER_CTA (S / CHUNKS)      // 512
#define NWARPS 8
#define NTHREADS (NWARPS * 32)         // 256
#define ROWS_PER_WARP (ROWS_PER_CTA / NWARPS)  // 64

// Scratch for split-softmax partials (allocation-free: __device__ globals)
__device__ float g_ctx_partial[B][CHUNKS][H];  // exp-weighted (unnormalized) context, per chunk
__device__ float g_m[B][CHUNKS];               // per-chunk running max
__device__ float g_l[B][CHUNKS];               // per-chunk running sum of exp

// ---------------------------------------------------------------------------
// Pass 1: single streaming read of encoder_outputs.
// Each CTA = (batch b, chunk c). Each warp owns ROWS_PER_WARP contiguous rows.
// Per row: load 4KB enc row (coalesced float4), dot with decoder state
// (register-resident), warp-reduce, write RAW score to attn region, and do an
// online-softmax update of the register-resident context accumulator.
// ---------------------------------------------------------------------------
__global__ void __launch_bounds__(NTHREADS, 2)
attn_pass1(const float* __restrict__ dec,   // [B, H]
           const float* __restrict__ enc,   // [B, S, H]
           float* __restrict__ attn_raw)    // [B, S] (raw scores for now)
{
    const int b    = blockIdx.y;
    const int c    = blockIdx.x;
    const int w    = threadIdx.x >> 5;
    const int lane = threadIdx.x & 31;

    // Decoder fragment: lane holds float4 indices {lane, lane+32, ..., lane+224}
    const float4* dec4 = (const float4*)(dec + (size_t)b * H);
    float4 d[8];
#pragma unroll
    for (int k = 0; k < 8; k++) d[k] = dec4[lane + 32 * k];

    float m = -INFINITY;
    float l = 0.0f;
    float4 ctx[8];
#pragma unroll
    for (int k = 0; k < 8; k++) ctx[k] = make_float4(0.f, 0.f, 0.f, 0.f);

    const int row0 = c * ROWS_PER_CTA + w * ROWS_PER_WARP;
    const float4* enc4_base = (const float4*)(enc + ((size_t)b * S) * H);

    for (int r = 0; r < ROWS_PER_WARP; r++) {
        const int s = row0 + r;
        const float4* e4 = enc4_base + (size_t)s * (H / 4);

        float4 e[8];
#pragma unroll
        for (int k = 0; k < 8; k++) e[k] = e4[lane + 32 * k];

        // Partial dot product
        float acc = 0.f;
#pragma unroll
        for (int k = 0; k < 8; k++) {
            acc += d[k].x * e[k].x;
            acc += d[k].y * e[k].y;
            acc += d[k].z * e[k].z;
            acc += d[k].w * e[k].w;
        }
        // Butterfly reduce: every lane ends with the full score
#pragma unroll
        for (int off = 16; off; off >>= 1)
            acc += __shfl_xor_sync(0xffffffffu, acc, off);

        if (lane == 0) attn_raw[(size_t)b * S + s] = acc;  // raw score; pass 2 normalizes

        // Online softmax update
        const float mn    = fmaxf(m, acc);
        const float alpha = __expf(m - mn);     // exp(-inf)=0 handles first iter
        const float wgt   = __expf(acc - mn);
        l = l * alpha + wgt;
#pragma unroll
        for (int k = 0; k < 8; k++) {
            ctx[k].x = ctx[k].x * alpha + wgt * e[k].x;
            ctx[k].y = ctx[k].y * alpha + wgt * e[k].y;
            ctx[k].z = ctx[k].z * alpha + wgt * e[k].z;
            ctx[k].w = ctx[k].w * alpha + wgt * e[k].w;
        }
        m = mn;
    }

    // ---- Merge 8 warps within the CTA ----
    __shared__ float sm[NWARPS];
    __shared__ float sl[NWARPS];
    __shared__ float sctx[NWARPS][H];   // 32 KB

    if (lane == 0) { sm[w] = m; sl[w] = l; }
    __syncthreads();

    float M = -INFINITY;
#pragma unroll
    for (int w2 = 0; w2 < NWARPS; w2++) M = fmaxf(M, sm[w2]);
    float L = 0.f;
#pragma unroll
    for (int w2 = 0; w2 < NWARPS; w2++) L += sl[w2] * __expf(sm[w2] - M);

    // Scale own partial to the CTA max, stash in smem
    const float scale = __expf(m - M);
    float4* my = (float4*)&sctx[w][0];
#pragma unroll
    for (int k = 0; k < 8; k++) {
        float4 v = ctx[k];
        v.x *= scale; v.y *= scale; v.z *= scale; v.w *= scale;
        my[lane + 32 * k] = v;
    }
    __syncthreads();

    // Cross-warp sum: thread t owns float4 position t (256 float4 = 1024 floats)
    const int t = threadIdx.x;
    float4 sum = make_float4(0.f, 0.f, 0.f, 0.f);
#pragma unroll
    for (int w2 = 0; w2 < NWARPS; w2++) {
        float4 v = ((float4*)&sctx[w2][0])[t];
        sum.x += v.x; sum.y += v.y; sum.z += v.z; sum.w += v.w;
    }
    ((float4*)&g_ctx_partial[b][c][0])[t] = sum;
    if (threadIdx.x == 0) { g_m[b][c] = M; g_l[b][c] = L; }
}

// ---------------------------------------------------------------------------
// Pass 2: per-batch merge of CHUNKS partials -> context; normalize attn.
// One CTA per batch; trivially cheap (~2 MB traffic total).
// ---------------------------------------------------------------------------
__global__ void __launch_bounds__(NTHREADS)
attn_pass2(float* __restrict__ out_ctx,   // [B, H]
           float* __restrict__ attn)      // [B, S] raw scores in, normalized out
{
    const int b = blockIdx.x;
    const int t = threadIdx.x;

    // Global max / sum (all threads redundantly; 8 floats each, L1-hit)
    float M = -INFINITY;
#pragma unroll
    for (int c = 0; c < CHUNKS; c++) M = fmaxf(M, g_m[b][c]);
    float L = 0.f;
    float esc[CHUNKS];
#pragma unroll
    for (int c = 0; c < CHUNKS; c++) {
        esc[c] = __expf(g_m[b][c] - M);
        L += g_l[b][c] * esc[c];
    }
    const float invL = 1.0f / L;

    // Context: thread t owns float4 position t
    float4 s = make_float4(0.f, 0.f, 0.f, 0.f);
#pragma unroll
    for (int c = 0; c < CHUNKS; c++) {
        float4 v = ((const float4*)&g_ctx_partial[b][c][0])[t];
        s.x += v.x * esc[c]; s.y += v.y * esc[c];
        s.z += v.z * esc[c]; s.w += v.w * esc[c];
    }
    s.x *= invL; s.y *= invL; s.z *= invL; s.w *= invL;
    ((float4*)(out_ctx + (size_t)b * H))[t] = s;

    // Normalize attention weights: 4096 floats = 1024 float4
    float4* a4 = (float4*)(attn + (size_t)b * S);
#pragma unroll
    for (int k = 0; k < 4; k++) {
        float4 v = a4[t + 256 * k];
        v.x = __expf(v.x - M) * invL;
        v.y = __expf(v.y - M) * invL;
        v.z = __expf(v.z - M) * invL;
        v.w = __expf(v.w - M) * invL;
        a4[t + 256 * k] = v;
    }
}

extern "C" void kernel_launch(void* const* d_in, const int* in_sizes, int n_in,
                              void* d_out, int out_size)
{
    const float* dec = (const float*)d_in[0];   // [B, H]
    const float* enc = (const float*)d_in[1];   // [B, S, H]
    float* out_ctx  = (float*)d_out;            // [B, H]
    float* out_attn = (float*)d_out + (size_t)B * H;  // [B, S]

    dim3 grid1(CHUNKS, B);
    attn_pass1<<<grid1, NTHREADS>>>(dec, enc, out_attn);
    attn_pass2<<<B, NTHREADS>>>(out_ctx, out_attn);
}